// round 15
// baseline (speedup 1.0000x reference)
#include <cuda_runtime.h>
#include <cuda_fp16.h>
#include <math.h>

#define BB 256
#define VV 50257
#define UU 65536
#define MM 3
#define NE (MM * VV)        // 150771 total (model, vocab) entries
#define NJB ((VV + 31) / 32) // 1571 j-blocks per row

// ---------------- scratch (device globals; no allocation at launch time) ----
__device__ __half g_probsT[(size_t)MM * VV * BB];  // [m][j][b], b contiguous, UNNORMALIZED exp (fp16)
__device__ float g_psum[(size_t)MM * BB * NJB];    // per-(m,b) partial sums (fp32)
__device__ float g_scale[MM * BB];                 // w_m / sum
__device__ int   g_count[UU];
__device__ int   g_off[UU + 1];
__device__ int   g_cursor[UU];
__device__ int   g_entries[NE];                    // packed pidx = m*VV + j

// ---------------- CSR inverse-map build ------------------------------------
__global__ void zero_counts() {
    int i = blockIdx.x * blockDim.x + threadIdx.x;
    if (i < UU) g_count[i] = 0;
}

__global__ void count_entries(const int* __restrict__ m0,
                              const int* __restrict__ m1,
                              const int* __restrict__ m2) {
    int idx = blockIdx.x * blockDim.x + threadIdx.x;
    if (idx >= NE) return;
    int m = idx / VV;
    int j = idx - m * VV;
    const int* mp = (m == 0) ? m0 : (m == 1) ? m1 : m2;
    atomicAdd(&g_count[mp[j]], 1);
}

// coalesced exclusive scan of 65536 counts: 1 block, 32 warps, warp-chunked
__global__ void scan_counts() {
    __shared__ int warp_tot[32];
    __shared__ int warp_pre[32];
    int t = threadIdx.x, lane = t & 31, w = t >> 5;
    const int CH = UU / 32;            // 2048 elements per warp
    int base = w * CH;

    int tot = 0;
    for (int i = lane; i < CH; i += 32) tot += g_count[base + i];
#pragma unroll
    for (int o = 16; o; o >>= 1) tot += __shfl_xor_sync(0xffffffffu, tot, o);
    if (lane == 0) warp_tot[w] = tot;
    __syncthreads();

    if (w == 0) {
        int v = warp_tot[lane];
        int s = v;
#pragma unroll
        for (int o = 1; o < 32; o <<= 1) {
            int x = __shfl_up_sync(0xffffffffu, s, o);
            if (lane >= o) s += x;
        }
        warp_pre[lane] = s - v;
        if (lane == 31) g_off[UU] = s;
    }
    __syncthreads();

    int run = warp_pre[w];
    for (int i = lane; i < CH; i += 32) {
        int v = g_count[base + i];
        int s = v;
#pragma unroll
        for (int o = 1; o < 32; o <<= 1) {
            int x = __shfl_up_sync(0xffffffffu, s, o);
            if (lane >= o) s += x;
        }
        int excl = run + s - v;
        g_off[base + i]    = excl;
        g_cursor[base + i] = excl;
        run += __shfl_sync(0xffffffffu, s, 31);
    }
}

__global__ void fill_entries(const int* __restrict__ m0,
                             const int* __restrict__ m1,
                             const int* __restrict__ m2) {
    int idx = blockIdx.x * blockDim.x + threadIdx.x;
    if (idx >= NE) return;
    int m = idx / VV;
    int j = idx - m * VV;
    const int* mp = (m == 0) ? m0 : (m == 1) ? m1 : m2;
    int u = mp[j];
    int pos = atomicAdd(&g_cursor[u], 1);
    g_entries[pos] = idx;   // pidx = m*VV + j
}

// canonicalize entry order within each bucket (determinism across replays)
__global__ void sort_buckets() {
    int u = blockIdx.x * blockDim.x + threadIdx.x;
    if (u >= UU) return;
    int s = g_off[u], e = g_off[u + 1];
    for (int i = s + 1; i < e; i++) {
        int key = g_entries[i];
        int k = i - 1;
        while (k >= s && g_entries[k] > key) { g_entries[k + 1] = g_entries[k]; k--; }
        g_entries[k + 1] = key;
    }
}

// ---------------- exp + transpose v4 (R14 version, unchanged) ----------------
__global__ void exp_transpose(const float* __restrict__ l0,
                              const float* __restrict__ l1,
                              const float* __restrict__ l2) {
    __shared__ __half tileh[32][66];  // [j_local][b_local], stride 66 halves (33 words)
    __shared__ float partx[32][9];    // [tx][warp] partial for b=2tx   (9 coprime 32)
    __shared__ float party[32][9];    // [tx][warp] partial for b=2tx+1
    int m  = blockIdx.z;
    int j0 = blockIdx.x * 32;
    int b0 = blockIdx.y * 64;
    const float* lg = (m == 0) ? l0 : (m == 1) ? l1 : l2;
    int tx = threadIdx.x, ty = threadIdx.y;   // (32, 8)

#pragma unroll
    for (int k = 0; k < 8; k++) {
        int bl = ty + k * 8;
        int j  = j0 + tx;
        float v = 0.f;
        if (j < VV) v = __expf(lg[(size_t)(b0 + bl) * VV + j]);
        tileh[tx][bl] = __float2half(v);
    }
    __syncthreads();

    float sx = 0.f, sy = 0.f;
#pragma unroll
    for (int k = 0; k < 4; k++) {
        int jl = ty + k * 8;
        int j  = j0 + jl;
        __half2 h = *reinterpret_cast<__half2*>(&tileh[jl][2 * tx]);  // bank (33jl+tx)
        float2 f = __half22float2(h);
        sx += f.x; sy += f.y;             // zeros for j>=VV tail
        if (j < VV)
            *reinterpret_cast<__half2*>(
                &g_probsT[(unsigned)((m * VV + j) * BB) + b0 + 2 * tx]) = h;
    }
    partx[tx][ty] = sx;
    party[tx][ty] = sy;
    __syncthreads();

    if (ty == 0) {
        float tx2 = 0.f, ty2 = 0.f;
#pragma unroll
        for (int i = 0; i < 8; i++) { tx2 += partx[tx][i]; ty2 += party[tx][i]; }
        g_psum[(size_t)(m * BB + b0 + 2 * tx) * NJB + blockIdx.x]     = tx2;
        g_psum[(size_t)(m * BB + b0 + 2 * tx + 1) * NJB + blockIdx.x] = ty2;
    }
}

// one block per (m,b) row: sum 1571 partials (coalesced), emit w_m/sum
__global__ void reduce_scale(const float* __restrict__ w) {
    int row = blockIdx.x;                 // 0 .. MM*BB-1
    int t = threadIdx.x, lane = t & 31, wp = t >> 5;
    const float* p = &g_psum[(size_t)row * NJB];
    float s = 0.f;
    for (int i = t; i < NJB; i += 256) s += p[i];
#pragma unroll
    for (int o = 16; o; o >>= 1) s += __shfl_xor_sync(0xffffffffu, s, o);
    __shared__ float ws[8];
    if (lane == 0) ws[wp] = s;
    __syncthreads();
    if (t == 0) {
        float tot = 0.f;
#pragma unroll
        for (int i = 0; i < 8; i++) tot += ws[i];
        g_scale[row] = w[row / BB] / tot;
    }
}

// ---------------- gather v8: run-accumulation in registers -------------------
// Entries are bucket-major sorted, so bucket id changes are warp-UNIFORM
// (tags come from shared memory): accumulate each bucket run in a register,
// flush once per bucket with a single STS (no LDS, no smem RMW chain).
// Tail uses exact uniform bounds — padding never enters accumulation.
#define GCAP 256
__global__ void __launch_bounds__(256) gather_union(float* __restrict__ out) {
    __shared__ float2 tile[32][129];          // [ul][b-pair], +1 pad
    __shared__ int soff[33];
    __shared__ int ent[GCAP + 8];
    __shared__ unsigned char eu[GCAP + 8];    // bits0-4 ul, bit6/7 model
    int t    = threadIdx.x;                   // 256 threads
    int half = t >> 7;                        // 0 or 1
    int tp   = t & 127;                       // batch-pair index
    int u0 = blockIdx.x * 32;

    if (t < 33) soff[t] = g_off[u0 + t];
    float2 sc0 = *reinterpret_cast<const float2*>(&g_scale[2 * tp]);
    float2 sc1 = *reinterpret_cast<const float2*>(&g_scale[BB + 2 * tp]);
    float2 sc2 = *reinterpret_cast<const float2*>(&g_scale[2 * BB + 2 * tp]);
    // zero own half's tile rows (covers empty buckets — they are never flushed)
#pragma unroll
    for (int r = 0; r < 16; r++) tile[half * 16 + r][tp] = make_float2(0.f, 0.f);
    __syncthreads();

    int s0 = soff[0];
    int n  = soff[32] - s0;                   // total entries (avg ~74)
    bool fits = (n <= GCAP);
    if (fits) {
        for (int k = t; k < n; k += 256) {
            int g    = s0 + k;
            int pidx = g_entries[g];
            ent[k] = pidx;
            int lo = 0, hi2 = 32;
            while (hi2 - lo > 1) { int mid = (lo + hi2) >> 1; if (soff[mid] <= g) lo = mid; else hi2 = mid; }
            int mt = (pidx >= 2 * VV) ? 128 : (pidx >= VV) ? 64 : 0;
            eu[k] = (unsigned char)(lo | mt);
        }
        for (int k = n + t; k < GCAP + 8; k += 256) { ent[k] = 0; eu[k] = 0; }
    }
    __syncthreads();

    const __half2* pt = reinterpret_cast<const __half2*>(g_probsT);
    int lo = soff[16 * half] - s0;
    int hi = soff[16 * half + 16] - s0;

    if (fits) {
        const int C = 8;
        float2 v[C]; int tg[C];
        // prime ring (guarded loads; guarded entries are never processed)
#pragma unroll
        for (int q = 0; q < C; q++) {
            int k = lo + q;
            float2 vv = make_float2(0.f, 0.f);
            int e = 0;
            if (k < hi) { e = eu[k]; vv = __half22float2(pt[(size_t)ent[k] * (BB / 2) + tp]); }
            v[q] = vv; tg[q] = e;
        }
        float2 acc = make_float2(0.f, 0.f);
        int cur_ul = -1;                       // -1 = no open run
        for (int base = lo; base < hi; base += C) {
            float2 vn[C]; int tn[C];
            int nb = base + C;
            // prefetch next chunk (independent of processing)
#pragma unroll
            for (int q = 0; q < C; q++) {
                int k = nb + q;
                float2 vv = make_float2(0.f, 0.f);
                int e = 0;
                if (k < hi) { e = eu[k]; vv = __half22float2(pt[(size_t)ent[k] * (BB / 2) + tp]); }
                vn[q] = vv; tn[q] = e;
            }
            int nproc = hi - base;             // uniform across threads
#pragma unroll
            for (int q = 0; q < C; q++) {
                if (q < nproc) {               // uniform guard
                    int e  = tg[q];
                    int ul = e & 31;
                    if (ul != cur_ul) {        // uniform: bucket transition
                        if (cur_ul >= 0) tile[cur_ul][tp] = acc;
                        acc = make_float2(0.f, 0.f);
                        cur_ul = ul;
                    }
                    float2 s = (e & 128) ? sc2 : (e & 64) ? sc1 : sc0;
                    acc.x += v[q].x * s.x;
                    acc.y += v[q].y * s.y;
                }
            }
#pragma unroll
            for (int q = 0; q < C; q++) { v[q] = vn[q]; tg[q] = tn[q]; }
        }
        if (cur_ul >= 0) tile[cur_ul][tp] = acc;
    } else {
        // fallback: bucket-serial, same accumulation order
        for (int ug = half * 16; ug < half * 16 + 16; ug++) {
            int bs = soff[ug], be = soff[ug + 1];
            float2 a = make_float2(0.f, 0.f);
            for (int g = bs; g < be; g++) {
                int p = g_entries[g];
                float2 s = (p >= 2 * VV) ? sc2 : (p >= VV) ? sc1 : sc0;
                float2 vv = __half22float2(pt[(size_t)p * (BB / 2) + tp]);
                a.x += vv.x * s.x;
                a.y += vv.y * s.y;
            }
            tile[ug][tp] = a;
        }
    }
    __syncthreads();
    for (int it = 0; it < 16; it++) {
        int ul = t & 31;
        int bp = (t >> 5) + it * 8;   // batch pair 0..127
        float2 v = tile[ul][bp];
        out[(size_t)(2 * bp) * UU + u0 + ul]     = v.x;
        out[(size_t)(2 * bp + 1) * UU + u0 + ul] = v.y;
    }
}

// ---------------- launch -------------------------------------------------------
// exp_transpose kept at our launch index 3 (ncu control: should stay ~44us;
// any total delta is gather v8).
extern "C" void kernel_launch(void* const* d_in, const int* in_sizes, int n_in,
                              void* d_out, int out_size) {
    const float* l0 = (const float*)d_in[0];
    const float* l1 = (const float*)d_in[1];
    const float* l2 = (const float*)d_in[2];
    const int*   m0 = (const int*)d_in[3];
    const int*   m1 = (const int*)d_in[4];
    const int*   m2 = (const int*)d_in[5];
    const float* w  = (const float*)d_in[6];
    float* out = (float*)d_out;

    zero_counts<<<UU / 256, 256>>>();
    count_entries<<<(NE + 255) / 256, 256>>>(m0, m1, m2);
    scan_counts<<<1, 1024>>>();
    exp_transpose<<<dim3(NJB, BB / 64, MM), dim3(32, 8)>>>(l0, l1, l2);
    fill_entries<<<(NE + 255) / 256, 256>>>(m0, m1, m2);
    sort_buckets<<<UU / 256, 256>>>();
    reduce_scale<<<MM * BB, 256>>>(w);
    gather_union<<<UU / 32, 256>>>(out);
}

// round 16
// speedup vs baseline: 1.1257x; 1.1257x over previous
#include <cuda_runtime.h>
#include <cuda_fp16.h>
#include <math.h>

#define BB 256
#define VV 50257
#define UU 65536
#define MM 3
#define NE (MM * VV)        // 150771 total (model, vocab) entries
#define NJB ((VV + 31) / 32) // 1571 j-blocks per row

// ---------------- scratch (device globals; no allocation at launch time) ----
__device__ __half g_probsT[(size_t)MM * VV * BB];  // [m][j][b], b contiguous, UNNORMALIZED exp (fp16)
__device__ float g_psum[(size_t)MM * BB * NJB];    // per-(m,b) partial sums (fp32)
__device__ float g_scale[MM * BB];                 // w_m / sum
__device__ int   g_count[UU];
__device__ int   g_off[UU + 1];
__device__ int   g_cursor[UU];
__device__ int   g_entries[NE];                    // packed pidx = m*VV + j

// ---------------- CSR inverse-map build ------------------------------------
__global__ void zero_counts() {
    int i = blockIdx.x * blockDim.x + threadIdx.x;
    if (i < UU) g_count[i] = 0;
}

__global__ void count_entries(const int* __restrict__ m0,
                              const int* __restrict__ m1,
                              const int* __restrict__ m2) {
    int idx = blockIdx.x * blockDim.x + threadIdx.x;
    if (idx >= NE) return;
    int m = idx / VV;
    int j = idx - m * VV;
    const int* mp = (m == 0) ? m0 : (m == 1) ? m1 : m2;
    atomicAdd(&g_count[mp[j]], 1);
}

// coalesced exclusive scan of 65536 counts: 1 block, 32 warps, warp-chunked
__global__ void scan_counts() {
    __shared__ int warp_tot[32];
    __shared__ int warp_pre[32];
    int t = threadIdx.x, lane = t & 31, w = t >> 5;
    const int CH = UU / 32;            // 2048 elements per warp
    int base = w * CH;

    int tot = 0;
    for (int i = lane; i < CH; i += 32) tot += g_count[base + i];
#pragma unroll
    for (int o = 16; o; o >>= 1) tot += __shfl_xor_sync(0xffffffffu, tot, o);
    if (lane == 0) warp_tot[w] = tot;
    __syncthreads();

    if (w == 0) {
        int v = warp_tot[lane];
        int s = v;
#pragma unroll
        for (int o = 1; o < 32; o <<= 1) {
            int x = __shfl_up_sync(0xffffffffu, s, o);
            if (lane >= o) s += x;
        }
        warp_pre[lane] = s - v;
        if (lane == 31) g_off[UU] = s;
    }
    __syncthreads();

    int run = warp_pre[w];
    for (int i = lane; i < CH; i += 32) {
        int v = g_count[base + i];
        int s = v;
#pragma unroll
        for (int o = 1; o < 32; o <<= 1) {
            int x = __shfl_up_sync(0xffffffffu, s, o);
            if (lane >= o) s += x;
        }
        int excl = run + s - v;
        g_off[base + i]    = excl;
        g_cursor[base + i] = excl;
        run += __shfl_sync(0xffffffffu, s, 31);
    }
}

__global__ void fill_entries(const int* __restrict__ m0,
                             const int* __restrict__ m1,
                             const int* __restrict__ m2) {
    int idx = blockIdx.x * blockDim.x + threadIdx.x;
    if (idx >= NE) return;
    int m = idx / VV;
    int j = idx - m * VV;
    const int* mp = (m == 0) ? m0 : (m == 1) ? m1 : m2;
    int u = mp[j];
    int pos = atomicAdd(&g_cursor[u], 1);
    g_entries[pos] = idx;   // pidx = m*VV + j
}

// canonicalize entry order within each bucket (determinism across replays)
__global__ void sort_buckets() {
    int u = blockIdx.x * blockDim.x + threadIdx.x;
    if (u >= UU) return;
    int s = g_off[u], e = g_off[u + 1];
    for (int i = s + 1; i < e; i++) {
        int key = g_entries[i];
        int k = i - 1;
        while (k >= s && g_entries[k] > key) { g_entries[k + 1] = g_entries[k]; k--; }
        g_entries[k + 1] = key;
    }
}

// ---------------- exp + transpose v4 (R14 version, unchanged) ----------------
__global__ void exp_transpose(const float* __restrict__ l0,
                              const float* __restrict__ l1,
                              const float* __restrict__ l2) {
    __shared__ __half tileh[32][66];  // [j_local][b_local], stride 66 halves (33 words)
    __shared__ float partx[32][9];    // [tx][warp] partial for b=2tx   (9 coprime 32)
    __shared__ float party[32][9];    // [tx][warp] partial for b=2tx+1
    int m  = blockIdx.z;
    int j0 = blockIdx.x * 32;
    int b0 = blockIdx.y * 64;
    const float* lg = (m == 0) ? l0 : (m == 1) ? l1 : l2;
    int tx = threadIdx.x, ty = threadIdx.y;   // (32, 8)

#pragma unroll
    for (int k = 0; k < 8; k++) {
        int bl = ty + k * 8;
        int j  = j0 + tx;
        float v = 0.f;
        if (j < VV) v = __expf(lg[(size_t)(b0 + bl) * VV + j]);
        tileh[tx][bl] = __float2half(v);
    }
    __syncthreads();

    float sx = 0.f, sy = 0.f;
#pragma unroll
    for (int k = 0; k < 4; k++) {
        int jl = ty + k * 8;
        int j  = j0 + jl;
        __half2 h = *reinterpret_cast<__half2*>(&tileh[jl][2 * tx]);  // bank (33jl+tx)
        float2 f = __half22float2(h);
        sx += f.x; sy += f.y;             // zeros for j>=VV tail
        if (j < VV)
            *reinterpret_cast<__half2*>(
                &g_probsT[(unsigned)((m * VV + j) * BB) + b0 + 2 * tx]) = h;
    }
    partx[tx][ty] = sx;
    party[tx][ty] = sy;
    __syncthreads();

    if (ty == 0) {
        float tx2 = 0.f, ty2 = 0.f;
#pragma unroll
        for (int i = 0; i < 8; i++) { tx2 += partx[tx][i]; ty2 += party[tx][i]; }
        g_psum[(size_t)(m * BB + b0 + 2 * tx) * NJB + blockIdx.x]     = tx2;
        g_psum[(size_t)(m * BB + b0 + 2 * tx + 1) * NJB + blockIdx.x] = ty2;
    }
}

// one block per (m,b) row: sum 1571 partials (coalesced), emit w_m/sum
__global__ void reduce_scale(const float* __restrict__ w) {
    int row = blockIdx.x;                 // 0 .. MM*BB-1
    int t = threadIdx.x, lane = t & 31, wp = t >> 5;
    const float* p = &g_psum[(size_t)row * NJB];
    float s = 0.f;
    for (int i = t; i < NJB; i += 256) s += p[i];
#pragma unroll
    for (int o = 16; o; o >>= 1) s += __shfl_xor_sync(0xffffffffu, s, o);
    __shared__ float ws[8];
    if (lane == 0) ws[wp] = s;
    __syncthreads();
    if (t == 0) {
        float tot = 0.f;
#pragma unroll
        for (int i = 0; i < 8; i++) tot += ws[i];
        g_scale[row] = w[row / BB] / tot;
    }
}

// ---------------- gather v7 (R13/R14 version — the proven best) --------------
#define GCAP 256
__global__ void __launch_bounds__(256) gather_union(float* __restrict__ out) {
    __shared__ float2 tile[32][129];          // [ul][b-pair], +1 pad
    __shared__ int soff[33];
    __shared__ int ent[GCAP + 8];
    __shared__ unsigned char eu[GCAP + 8];    // bits0-4 ul, bit6/7 model; 255=inactive
    int t    = threadIdx.x;                   // 256 threads
    int half = t >> 7;                        // 0 or 1
    int tp   = t & 127;                       // batch-pair index
    int u0 = blockIdx.x * 32;

    if (t < 33) soff[t] = g_off[u0 + t];
    float2 sc0 = *reinterpret_cast<const float2*>(&g_scale[2 * tp]);
    float2 sc1 = *reinterpret_cast<const float2*>(&g_scale[BB + 2 * tp]);
    float2 sc2 = *reinterpret_cast<const float2*>(&g_scale[2 * BB + 2 * tp]);
#pragma unroll
    for (int r = 0; r < 16; r++) tile[half * 16 + r][tp] = make_float2(0.f, 0.f);
    __syncthreads();

    int s0 = soff[0];
    int n  = soff[32] - s0;                   // total entries (avg ~74)
    bool fits = (n <= GCAP);
    if (fits) {
        for (int k = t; k < n; k += 256) {
            int g    = s0 + k;
            int pidx = g_entries[g];
            ent[k] = pidx;
            int lo = 0, hi2 = 32;
            while (hi2 - lo > 1) { int mid = (lo + hi2) >> 1; if (soff[mid] <= g) lo = mid; else hi2 = mid; }
            int mt = (pidx >= 2 * VV) ? 128 : (pidx >= VV) ? 64 : 0;
            eu[k] = (unsigned char)(lo | mt);
        }
        for (int k = n + t; k < GCAP + 8; k += 256) { ent[k] = 0; eu[k] = 255; }
    }
    __syncthreads();

    const __half2* pt = reinterpret_cast<const __half2*>(g_probsT);
    int lo = soff[16 * half] - s0;
    int hi = soff[16 * half + 16] - s0;

    if (fits) {
        const int C = 8;
        float2 v[C]; int tg[C];
#pragma unroll
        for (int q = 0; q < C; q++) {
            int k = lo + q;
            float2 vv = make_float2(0.f, 0.f);
            int e = 255;
            if (k < hi) { e = eu[k]; vv = __half22float2(pt[(size_t)ent[k] * (BB / 2) + tp]); }
            v[q] = vv; tg[q] = e;
        }
        for (int base = lo; base < hi; base += C) {
            float2 vn[C]; int tn[C];
            int nb = base + C;
#pragma unroll
            for (int q = 0; q < C; q++) {
                int k = nb + q;
                float2 vv = make_float2(0.f, 0.f);
                int e = 255;
                if (k < hi) { e = eu[k]; vv = __half22float2(pt[(size_t)ent[k] * (BB / 2) + tp]); }
                vn[q] = vv; tn[q] = e;
            }
#pragma unroll
            for (int q = 0; q < C; q++) {
                int e = tg[q];
                float2 s = (e >= 128) ? sc2 : (e >= 64) ? sc1 : sc0;
                int ul = (e == 255) ? (half << 4) : (e & 31);
                float2* c = &tile[ul][tp];
                c->x += v[q].x * s.x;
                c->y += v[q].y * s.y;
            }
#pragma unroll
            for (int q = 0; q < C; q++) { v[q] = vn[q]; tg[q] = tn[q]; }
        }
    } else {
        for (int ug = half * 16; ug < half * 16 + 16; ug++) {
            int bs = soff[ug], be = soff[ug + 1];
            float2 a = make_float2(0.f, 0.f);
            for (int g = bs; g < be; g++) {
                int p = g_entries[g];
                float2 s = (p >= 2 * VV) ? sc2 : (p >= VV) ? sc1 : sc0;
                float2 vv = __half22float2(pt[(size_t)p * (BB / 2) + tp]);
                a.x += vv.x * s.x;
                a.y += vv.y * s.y;
            }
            tile[ug][tp] = a;
        }
    }
    __syncthreads();
    for (int it = 0; it < 16; it++) {
        int ul = t & 31;
        int bp = (t >> 5) + it * 8;   // batch pair 0..127
        float2 v = tile[ul][bp];
        out[(size_t)(2 * bp) * UU + u0 + ul]     = v.x;
        out[(size_t)(2 * bp + 1) * UU + u0 + ul] = v.y;
    }
}

// ---------------- launch -------------------------------------------------------
// Two-branch DAG: CSR chain (maps only) runs on a forked non-blocking stream
// concurrently with exp_transpose+reduce_scale (logits only); gather joins both.
// Event record/wait become graph edges under capture (documented multi-branch
// capture pattern). Same work, same dependencies, no syncs, no allocs in the
// launch path. Launch ordinals keep exp_transpose as the 4th kernel (ncu slot).
extern "C" void kernel_launch(void* const* d_in, const int* in_sizes, int n_in,
                              void* d_out, int out_size) {
    const float* l0 = (const float*)d_in[0];
    const float* l1 = (const float*)d_in[1];
    const float* l2 = (const float*)d_in[2];
    const int*   m0 = (const int*)d_in[3];
    const int*   m1 = (const int*)d_in[4];
    const int*   m2 = (const int*)d_in[5];
    const float* w  = (const float*)d_in[6];
    float* out = (float*)d_out;

    static cudaStream_t s2 = nullptr;
    static cudaEvent_t ev_fork = nullptr, ev_join = nullptr;
    if (s2 == nullptr) {
        cudaStreamCreateWithFlags(&s2, cudaStreamNonBlocking);
        cudaEventCreateWithFlags(&ev_fork, cudaEventDisableTiming);
        cudaEventCreateWithFlags(&ev_join, cudaEventDisableTiming);
    }

    // fork: s2 inherits the main stream's current position
    cudaEventRecord(ev_fork, 0);
    cudaStreamWaitEvent(s2, ev_fork, 0);

    // CSR branch (independent of logits) on s2
    zero_counts<<<UU / 256, 256, 0, s2>>>();
    count_entries<<<(NE + 255) / 256, 256, 0, s2>>>(m0, m1, m2);
    scan_counts<<<1, 1024, 0, s2>>>();

    // main branch: exp (4th kernel launch overall -> ncu capture slot)
    exp_transpose<<<dim3(NJB, BB / 64, MM), dim3(32, 8)>>>(l0, l1, l2);

    // rest of CSR branch
    fill_entries<<<(NE + 255) / 256, 256, 0, s2>>>(m0, m1, m2);
    sort_buckets<<<UU / 256, 256, 0, s2>>>();

    // main branch continues
    reduce_scale<<<MM * BB, 256>>>(w);

    // join: gather needs both branches
    cudaEventRecord(ev_join, s2);
    cudaStreamWaitEvent(0, ev_join, 0);
    gather_union<<<UU / 32, 256>>>(out);
}